// round 4
// baseline (speedup 1.0000x reference)
#include <cuda_runtime.h>
#include <cuda_bf16.h>
#include <cstdint>

#define Nq 400000
#define Kq 27
#define Cq 64
#define Dq 128
#define Hq 128
#define Wq 128
#define EPSq 1e-5f
#define TABLE_SIZE (2 * Dq * Hq * Wq)   // 4,194,304

// ---- scratch (device globals; allocation-free rule) ----
__device__ int   g_table[TABLE_SIZE];
__device__ int   g_nbr[Kq * Nq];
// activations as bf16 hi/lo pairs (precision doubling)
__device__ __nv_bfloat16 g_h1[(size_t)Nq * Cq];
__device__ __nv_bfloat16 g_l1[(size_t)Nq * Cq];
__device__ __nv_bfloat16 g_h2[(size_t)Nq * Cq];
__device__ __nv_bfloat16 g_l2[(size_t)Nq * Cq];
// pre-packed B fragments: [k][part(hi/lo)][kc(4)][n8(8)][lane(32)] x uint2
__device__ uint2 g_wf2[Kq * 2048];
__device__ uint2 g_wf3[Kq * 2048];

// ---------------------------------------------------------------------------
// helpers
// ---------------------------------------------------------------------------
__device__ __forceinline__ uint32_t smem_u32(const void* p) {
    uint32_t a;
    asm("{ .reg .u64 t; cvta.to.shared.u64 t, %1; cvt.u32.u64 %0, t; }" : "=r"(a) : "l"(p));
    return a;
}

__device__ __forceinline__ void mma_bf16(float* d, const uint32_t* a, uint32_t b0, uint32_t b1) {
    asm volatile(
        "mma.sync.aligned.m16n8k16.row.col.f32.bf16.bf16.f32 "
        "{%0,%1,%2,%3}, {%4,%5,%6,%7}, {%8,%9}, {%0,%1,%2,%3};"
        : "+f"(d[0]), "+f"(d[1]), "+f"(d[2]), "+f"(d[3])
        : "r"(a[0]), "r"(a[1]), "r"(a[2]), "r"(a[3]), "r"(b0), "r"(b1));
}

__device__ __forceinline__ void ldm_x4(uint32_t* a, uint32_t addr) {
    asm volatile(
        "ldmatrix.sync.aligned.m8n8.x4.shared.b16 {%0,%1,%2,%3}, [%4];"
        : "=r"(a[0]), "=r"(a[1]), "=r"(a[2]), "=r"(a[3]) : "r"(addr));
}

__device__ __forceinline__ void cp16(uint32_t dst, const void* src, uint32_t srcsize) {
    asm volatile("cp.async.cg.shared.global [%0], [%1], 16, %2;"
                 :: "r"(dst), "l"(src), "r"(srcsize) : "memory");
}
__device__ __forceinline__ void cp_commit() {
    asm volatile("cp.async.commit_group;" ::: "memory");
}

// ---------------------------------------------------------------------------
// rulebook
// ---------------------------------------------------------------------------
__global__ void init_table_kernel() {
    int i = blockIdx.x * blockDim.x + threadIdx.x;
    ((int4*)g_table)[i] = make_int4(-1, -1, -1, -1);
}

__global__ void scatter_kernel(const int* __restrict__ coords) {
    int i = blockIdx.x * blockDim.x + threadIdx.x;
    if (i >= Nq) return;
    int b = coords[i * 4 + 0], z = coords[i * 4 + 1];
    int y = coords[i * 4 + 2], x = coords[i * 4 + 3];
    g_table[((b * Dq + z) * Hq + y) * Wq + x] = i;
}

__global__ void build_nbr_kernel(const int* __restrict__ coords) {
    int i = blockIdx.x * blockDim.x + threadIdx.x;
    if (i >= Nq) return;
    int b = coords[i * 4 + 0], z = coords[i * 4 + 1];
    int y = coords[i * 4 + 2], x = coords[i * 4 + 3];
    #pragma unroll
    for (int k = 0; k < Kq; k++) {
        int dz = k / 9 - 1, dy = (k / 3) % 3 - 1, dx = k % 3 - 1;
        int nz = z + dz, ny = y + dy, nx = x + dx;
        int r = -1;
        if (nz >= 0 && nz < Dq && ny >= 0 && ny < Hq && nx >= 0 && nx < Wq)
            r = g_table[((b * Dq + nz) * Hq + ny) * Wq + nx];
        g_nbr[k * Nq + i] = r;
    }
}

// ---------------------------------------------------------------------------
// weight prep: w[k][cin][cout] fp32 -> per-thread mma B fragments, bf16 hi/lo
// ---------------------------------------------------------------------------
__global__ void prep_w_kernel(const float* __restrict__ w, uint2* __restrict__ frag) {
    int idx = blockIdx.x * blockDim.x + threadIdx.x;
    if (idx >= Kq * 2048) return;
    int lane = idx & 31;
    int n8   = (idx >> 5) & 7;
    int kc   = (idx >> 8) & 3;
    int part = (idx >> 10) & 1;
    int k    = idx >> 11;

    int n  = n8 * 8 + (lane >> 2);
    int c0 = kc * 16 + (lane & 3) * 2;
    uint32_t r[2];
    #pragma unroll
    for (int h = 0; h < 2; h++) {
        uint32_t packed = 0;
        #pragma unroll
        for (int e = 0; e < 2; e++) {
            float x = w[(k * 64 + (c0 + h * 8 + e)) * 64 + n];
            __nv_bfloat16 hi = __float2bfloat16_rn(x);
            __nv_bfloat16 val = part == 0 ? hi
                                : __float2bfloat16_rn(x - __bfloat162float(hi));
            uint16_t bits = *(uint16_t*)&val;
            packed |= (uint32_t)bits << (16 * e);
        }
        r[h] = packed;
    }
    frag[idx] = make_uint2(r[0], r[1]);
}

// ---------------------------------------------------------------------------
// layer 1 (cin=1): 128-voxel tiles, 256 threads, writes bf16 hi/lo
// ---------------------------------------------------------------------------
__global__ void __launch_bounds__(256) layer1_kernel(
    const float* __restrict__ feats, const float* __restrict__ w,
    const float* __restrict__ bias,
    const float* __restrict__ gg, const float* __restrict__ be,
    const float* __restrict__ mm, const float* __restrict__ vv,
    __nv_bfloat16* __restrict__ oh, __nv_bfloat16* __restrict__ ol)
{
    __shared__ float s_w[Kq * Cq];
    __shared__ float s_f[Kq * 128];
    __shared__ float s_scale[Cq], s_shift[Cq];

    const int tid = threadIdx.x;
    const int v0  = blockIdx.x * 128;

    if (tid < Cq) {
        float sc = gg[tid] * rsqrtf(vv[tid] + EPSq);
        s_scale[tid] = sc;
        s_shift[tid] = (bias[tid] - mm[tid]) * sc + be[tid];
    }
    for (int i = tid; i < Kq * Cq; i += 256) s_w[i] = w[i];

    #pragma unroll 7
    for (int idx = tid; idx < Kq * 128; idx += 256) {
        int k = idx >> 7, v = idx & 127;
        int n = g_nbr[k * Nq + v0 + v];
        s_f[idx] = (n >= 0) ? feats[n] : 0.f;
    }
    __syncthreads();

    const int c  = tid & 63;
    const int vg = tid >> 6;
    float acc[32];
    #pragma unroll
    for (int i = 0; i < 32; i++) acc[i] = 0.f;

    for (int k = 0; k < Kq; k++) {
        float wk = s_w[k * Cq + c];
        const float* fp = &s_f[k * 128 + vg * 32];
        #pragma unroll
        for (int i = 0; i < 32; i++) acc[i] = fmaf(fp[i], wk, acc[i]);
    }
    const float sc = s_scale[c], sh = s_shift[c];
    #pragma unroll
    for (int i = 0; i < 32; i++) {
        float r = fmaxf(fmaf(acc[i], sc, sh), 0.f);
        size_t o = (size_t)(v0 + vg * 32 + i) * Cq + c;
        __nv_bfloat16 hi = __float2bfloat16_rn(r);
        oh[o] = hi;
        ol[o] = __float2bfloat16_rn(r - __bfloat162float(hi));
    }
}

// ---------------------------------------------------------------------------
// conv64 via mma.sync bf16x3. 128 voxels/CTA, 256 threads (8 warps x 16 vox).
// 2 CTAs/SM (smem 98.8KB each) to hide LDS/barrier/cp.async latency behind
// the other CTA's MMA stream.
// ---------------------------------------------------------------------------
#define SM_A    0
#define SM_B    65536
#define SM_SCL  (SM_B + 32768)
#define SM_SFT  (SM_SCL + 256)
#define SM_TOT  (SM_SFT + 256)

__device__ __forceinline__ void stage_offset(
    int kk, int buf, int v0, int tid, uint32_t sbase,
    const __nv_bfloat16* __restrict__ xh, const __nv_bfloat16* __restrict__ xl,
    const uint2* __restrict__ wfrag)
{
    int row  = tid & 127;
    int part = tid >> 7;
    int n = __ldg(&g_nbr[kk * Nq + v0 + row]);
    const __nv_bfloat16* src = (part ? xl : xh) + (size_t)(n < 0 ? 0 : n) * Cq;
    uint32_t srcsz = (n >= 0) ? 16u : 0u;
    uint32_t dbase = sbase + SM_A + buf * 32768 + part * 16384 + row * 128;
    uint32_t swz = (row & 7) << 4;
    #pragma unroll
    for (int j = 0; j < 8; j++)
        cp16(dbase + (((uint32_t)(j << 4)) ^ swz), src + j * 8, srcsz);
    const char* wsrc = (const char*)(wfrag + kk * 2048) + tid * 64;
    uint32_t wdst = sbase + SM_B + buf * 16384 + tid * 64;
    #pragma unroll
    for (int j = 0; j < 4; j++)
        cp16(wdst + j * 16, wsrc + j * 16, 16u);
}

__global__ void __launch_bounds__(256, 2) conv_mma_kernel(
    const __nv_bfloat16* __restrict__ xh, const __nv_bfloat16* __restrict__ xl,
    const uint2* __restrict__ wfrag,
    const float* __restrict__ bias,
    const float* __restrict__ gg, const float* __restrict__ be,
    const float* __restrict__ mm, const float* __restrict__ vv,
    float* __restrict__ out_f32,
    __nv_bfloat16* __restrict__ oh, __nv_bfloat16* __restrict__ ol,
    int outmode)
{
    extern __shared__ char smc[];
    const uint32_t sbase = smem_u32(smc);
    const int tid  = threadIdx.x;
    const int lane = tid & 31;
    const int warp = tid >> 5;
    const int v0   = blockIdx.x * 128;

    float* s_scale = (float*)(smc + SM_SCL);
    float* s_shift = (float*)(smc + SM_SFT);
    if (tid < Cq) {
        float sc = gg[tid] * rsqrtf(vv[tid] + EPSq);
        s_scale[tid] = sc;
        s_shift[tid] = (bias[tid] - mm[tid]) * sc + be[tid];
    }

    stage_offset(0, 0, v0, tid, sbase, xh, xl, wfrag);
    cp_commit();
    stage_offset(1, 1, v0, tid, sbase, xh, xl, wfrag);
    cp_commit();

    float d[8][4];
    #pragma unroll
    for (int i = 0; i < 8; i++)
        #pragma unroll
        for (int j = 0; j < 4; j++) d[i][j] = 0.f;

    const int rowl = (lane & 7) | (lane & 8);
    const int row  = warp * 16 + rowl;
    const uint32_t rbase = row * 128;
    const uint32_t swz   = (row & 7) << 4;
    const uint32_t colh  = (lane & 16);

    for (int k = 0; k < Kq; k++) {
        const int buf = k & 1;
        if (k == Kq - 1) asm volatile("cp.async.wait_group 0;" ::: "memory");
        else             asm volatile("cp.async.wait_group 1;" ::: "memory");
        __syncthreads();

        const uint32_t sa = sbase + SM_A + buf * 32768 + rbase;
        const uint2* sb = (const uint2*)(smc + SM_B + buf * 16384);

        #pragma unroll
        for (int kc = 0; kc < 4; kc++) {
            uint32_t boff = ((uint32_t)((kc << 5) | colh)) ^ swz;
            uint32_t ahi[4], alo[4];
            ldm_x4(ahi, sa + boff);
            ldm_x4(alo, sa + boff + 16384);
            #pragma unroll
            for (int n8 = 0; n8 < 8; n8++) {
                uint2 bh = sb[(kc * 8 + n8) * 32 + lane];
                uint2 bl = sb[((4 + kc) * 8 + n8) * 32 + lane];
                mma_bf16(d[n8], ahi, bh.x, bh.y);
                mma_bf16(d[n8], alo, bh.x, bh.y);
                mma_bf16(d[n8], ahi, bl.x, bl.y);
            }
        }
        __syncthreads();
        if (k < Kq - 2) {
            stage_offset(k + 2, buf, v0, tid, sbase, xh, xl, wfrag);
            cp_commit();
        }
    }

    const int r0 = v0 + warp * 16 + (lane >> 2);
    const int r1 = r0 + 8;
    #pragma unroll
    for (int n8 = 0; n8 < 8; n8++) {
        int col = n8 * 8 + (lane & 3) * 2;
        float sc0 = s_scale[col], sc1 = s_scale[col + 1];
        float sh0 = s_shift[col], sh1 = s_shift[col + 1];
        float o00 = fmaxf(fmaf(d[n8][0], sc0, sh0), 0.f);
        float o01 = fmaxf(fmaf(d[n8][1], sc1, sh1), 0.f);
        float o10 = fmaxf(fmaf(d[n8][2], sc0, sh0), 0.f);
        float o11 = fmaxf(fmaf(d[n8][3], sc1, sh1), 0.f);
        if (outmode == 0) {
            *(float2*)(out_f32 + (size_t)r0 * Cq + col) = make_float2(o00, o01);
            *(float2*)(out_f32 + (size_t)r1 * Cq + col) = make_float2(o10, o11);
        } else {
            __nv_bfloat16 h00 = __float2bfloat16_rn(o00);
            __nv_bfloat16 h01 = __float2bfloat16_rn(o01);
            __nv_bfloat16 h10 = __float2bfloat16_rn(o10);
            __nv_bfloat16 h11 = __float2bfloat16_rn(o11);
            __nv_bfloat162 hv0; hv0.x = h00; hv0.y = h01;
            __nv_bfloat162 hv1; hv1.x = h10; hv1.y = h11;
            *(__nv_bfloat162*)(oh + (size_t)r0 * Cq + col) = hv0;
            *(__nv_bfloat162*)(oh + (size_t)r1 * Cq + col) = hv1;
            __nv_bfloat162 lv0, lv1;
            lv0.x = __float2bfloat16_rn(o00 - __bfloat162float(h00));
            lv0.y = __float2bfloat16_rn(o01 - __bfloat162float(h01));
            lv1.x = __float2bfloat16_rn(o10 - __bfloat162float(h10));
            lv1.y = __float2bfloat16_rn(o11 - __bfloat162float(h11));
            *(__nv_bfloat162*)(ol + (size_t)r0 * Cq + col) = lv0;
            *(__nv_bfloat162*)(ol + (size_t)r1 * Cq + col) = lv1;
        }
    }
}

// ---------------------------------------------------------------------------
extern "C" void kernel_launch(void* const* d_in, const int* in_sizes, int n_in,
                              void* d_out, int out_size)
{
    const float* feats  = (const float*)d_in[0];
    const int*   coords = (const int*)  d_in[1];
    const float* w1 = (const float*)d_in[2];
    const float* b1 = (const float*)d_in[3];
    const float* g1 = (const float*)d_in[4];
    const float* be1= (const float*)d_in[5];
    const float* m1 = (const float*)d_in[6];
    const float* v1 = (const float*)d_in[7];
    const float* w2 = (const float*)d_in[8];
    const float* b2 = (const float*)d_in[9];
    const float* g2 = (const float*)d_in[10];
    const float* be2= (const float*)d_in[11];
    const float* m2 = (const float*)d_in[12];
    const float* v2 = (const float*)d_in[13];
    const float* w3 = (const float*)d_in[14];
    const float* b3 = (const float*)d_in[15];
    const float* g3 = (const float*)d_in[16];
    const float* be3= (const float*)d_in[17];
    const float* m3 = (const float*)d_in[18];
    const float* v3 = (const float*)d_in[19];
    float* out = (float*)d_out;

    cudaFuncSetAttribute(conv_mma_kernel,
                         cudaFuncAttributeMaxDynamicSharedMemorySize, SM_TOT);

    uint2 *wf2, *wf3;
    cudaGetSymbolAddress((void**)&wf2, g_wf2);
    cudaGetSymbolAddress((void**)&wf3, g_wf3);
    __nv_bfloat16 *h1, *l1, *h2, *l2;
    cudaGetSymbolAddress((void**)&h1, g_h1);
    cudaGetSymbolAddress((void**)&l1, g_l1);
    cudaGetSymbolAddress((void**)&h2, g_h2);
    cudaGetSymbolAddress((void**)&l2, g_l2);

    init_table_kernel<<<4096, 256>>>();
    scatter_kernel<<<(Nq + 255) / 256, 256>>>(coords);
    prep_w_kernel<<<(Kq * 2048 + 255) / 256, 256>>>(w2, wf2);
    prep_w_kernel<<<(Kq * 2048 + 255) / 256, 256>>>(w3, wf3);
    build_nbr_kernel<<<(Nq + 255) / 256, 256>>>(coords);

    layer1_kernel<<<Nq / 128, 256>>>(feats, w1, b1, g1, be1, m1, v1, h1, l1);
    conv_mma_kernel<<<Nq / 128, 256, SM_TOT>>>(h1, l1, wf2, b2, g2, be2, m2, v2,
                                               nullptr, h2, l2, 1);
    conv_mma_kernel<<<Nq / 128, 256, SM_TOT>>>(h2, l2, wf3, b3, g3, be3, m3, v3,
                                               out, nullptr, nullptr, 0);
}

// round 5
// speedup vs baseline: 1.6245x; 1.6245x over previous
#include <cuda_runtime.h>
#include <cuda_fp16.h>
#include <cstdint>

#define Nq 400000
#define Kq 27
#define Cq 64
#define Dq 128
#define Hq 128
#define Wq 128
#define EPSq 1e-5f
#define TABLE_SIZE (2 * Dq * Hq * Wq)   // 4,194,304

// ---- scratch (device globals; allocation-free rule) ----
__device__ int   g_table[TABLE_SIZE];
__device__ int   g_nbr[Kq * Nq];
// activations: single fp16 (weights carry the precision via hi/lo split)
__device__ __half g_a1[(size_t)Nq * Cq];
__device__ __half g_a2[(size_t)Nq * Cq];
// pre-packed B fragments: [k][part(hi/lo)][kc(4)][n8(8)][lane(32)] x uint2 (fp16)
__device__ uint2 g_wf2[Kq * 2048];
__device__ uint2 g_wf3[Kq * 2048];

// ---------------------------------------------------------------------------
// helpers
// ---------------------------------------------------------------------------
__device__ __forceinline__ uint32_t smem_u32(const void* p) {
    uint32_t a;
    asm("{ .reg .u64 t; cvta.to.shared.u64 t, %1; cvt.u32.u64 %0, t; }" : "=r"(a) : "l"(p));
    return a;
}

__device__ __forceinline__ void mma_f16(float* d, const uint32_t* a, uint32_t b0, uint32_t b1) {
    asm volatile(
        "mma.sync.aligned.m16n8k16.row.col.f32.f16.f16.f32 "
        "{%0,%1,%2,%3}, {%4,%5,%6,%7}, {%8,%9}, {%0,%1,%2,%3};"
        : "+f"(d[0]), "+f"(d[1]), "+f"(d[2]), "+f"(d[3])
        : "r"(a[0]), "r"(a[1]), "r"(a[2]), "r"(a[3]), "r"(b0), "r"(b1));
}

__device__ __forceinline__ void ldm_x4(uint32_t* a, uint32_t addr) {
    asm volatile(
        "ldmatrix.sync.aligned.m8n8.x4.shared.b16 {%0,%1,%2,%3}, [%4];"
        : "=r"(a[0]), "=r"(a[1]), "=r"(a[2]), "=r"(a[3]) : "r"(addr));
}

__device__ __forceinline__ void cp16(uint32_t dst, const void* src, uint32_t srcsize) {
    asm volatile("cp.async.cg.shared.global [%0], [%1], 16, %2;"
                 :: "r"(dst), "l"(src), "r"(srcsize) : "memory");
}
__device__ __forceinline__ void cp_commit() {
    asm volatile("cp.async.commit_group;" ::: "memory");
}

// ---------------------------------------------------------------------------
// rulebook
// ---------------------------------------------------------------------------
__global__ void init_table_kernel() {
    int i = blockIdx.x * blockDim.x + threadIdx.x;
    ((int4*)g_table)[i] = make_int4(-1, -1, -1, -1);
}

__global__ void scatter_kernel(const int* __restrict__ coords) {
    int i = blockIdx.x * blockDim.x + threadIdx.x;
    if (i >= Nq) return;
    int b = coords[i * 4 + 0], z = coords[i * 4 + 1];
    int y = coords[i * 4 + 2], x = coords[i * 4 + 3];
    g_table[((b * Dq + z) * Hq + y) * Wq + x] = i;
}

__global__ void build_nbr_kernel(const int* __restrict__ coords) {
    int i = blockIdx.x * blockDim.x + threadIdx.x;
    if (i >= Nq) return;
    int b = coords[i * 4 + 0], z = coords[i * 4 + 1];
    int y = coords[i * 4 + 2], x = coords[i * 4 + 3];
    #pragma unroll
    for (int k = 0; k < Kq; k++) {
        int dz = k / 9 - 1, dy = (k / 3) % 3 - 1, dx = k % 3 - 1;
        int nz = z + dz, ny = y + dy, nx = x + dx;
        int r = -1;
        if (nz >= 0 && nz < Dq && ny >= 0 && ny < Hq && nx >= 0 && nx < Wq)
            r = g_table[((b * Dq + nz) * Hq + ny) * Wq + nx];
        g_nbr[k * Nq + i] = r;
    }
}

// ---------------------------------------------------------------------------
// weight prep: w[k][cin][cout] fp32 -> mma B fragments, fp16 hi/lo split
// ---------------------------------------------------------------------------
__global__ void prep_w_kernel(const float* __restrict__ w, uint2* __restrict__ frag) {
    int idx = blockIdx.x * blockDim.x + threadIdx.x;
    if (idx >= Kq * 2048) return;
    int lane = idx & 31;
    int n8   = (idx >> 5) & 7;
    int kc   = (idx >> 8) & 3;
    int part = (idx >> 10) & 1;
    int k    = idx >> 11;

    int n  = n8 * 8 + (lane >> 2);
    int c0 = kc * 16 + (lane & 3) * 2;
    uint32_t r[2];
    #pragma unroll
    for (int h = 0; h < 2; h++) {
        uint32_t packed = 0;
        #pragma unroll
        for (int e = 0; e < 2; e++) {
            float x = w[(k * 64 + (c0 + h * 8 + e)) * 64 + n];
            __half hi = __float2half_rn(x);
            __half val = part == 0 ? hi : __float2half_rn(x - __half2float(hi));
            uint16_t bits = *(uint16_t*)&val;
            packed |= (uint32_t)bits << (16 * e);
        }
        r[h] = packed;
    }
    frag[idx] = make_uint2(r[0], r[1]);
}

// ---------------------------------------------------------------------------
// layer 1 (cin=1): 128-voxel tiles, 256 threads, writes single fp16
// ---------------------------------------------------------------------------
__global__ void __launch_bounds__(256) layer1_kernel(
    const float* __restrict__ feats, const float* __restrict__ w,
    const float* __restrict__ bias,
    const float* __restrict__ gg, const float* __restrict__ be,
    const float* __restrict__ mm, const float* __restrict__ vv,
    __half* __restrict__ oa)
{
    __shared__ float s_w[Kq * Cq];
    __shared__ float s_f[Kq * 128];
    __shared__ float s_scale[Cq], s_shift[Cq];

    const int tid = threadIdx.x;
    const int v0  = blockIdx.x * 128;

    if (tid < Cq) {
        float sc = gg[tid] * rsqrtf(vv[tid] + EPSq);
        s_scale[tid] = sc;
        s_shift[tid] = (bias[tid] - mm[tid]) * sc + be[tid];
    }
    for (int i = tid; i < Kq * Cq; i += 256) s_w[i] = w[i];

    #pragma unroll 7
    for (int idx = tid; idx < Kq * 128; idx += 256) {
        int k = idx >> 7, v = idx & 127;
        int n = g_nbr[k * Nq + v0 + v];
        s_f[idx] = (n >= 0) ? feats[n] : 0.f;
    }
    __syncthreads();

    const int c  = tid & 63;
    const int vg = tid >> 6;
    float acc[32];
    #pragma unroll
    for (int i = 0; i < 32; i++) acc[i] = 0.f;

    for (int k = 0; k < Kq; k++) {
        float wk = s_w[k * Cq + c];
        const float* fp = &s_f[k * 128 + vg * 32];
        #pragma unroll
        for (int i = 0; i < 32; i++) acc[i] = fmaf(fp[i], wk, acc[i]);
    }
    const float sc = s_scale[c], sh = s_shift[c];
    #pragma unroll
    for (int i = 0; i < 32; i++) {
        float r = fmaxf(fmaf(acc[i], sc, sh), 0.f);
        oa[(size_t)(v0 + vg * 32 + i) * Cq + c] = __float2half_rn(r);
    }
}

// ---------------------------------------------------------------------------
// conv64 via mma.sync fp16 2-term (A exact-in-fp16 rounded act, B hi/lo split).
// 256 voxels/CTA, 256 threads (8 warps x 16 rows x 2 row-tiles).
// smem: A [2 buf][256 rows][128B swizzled] = 64KB, B [2 buf][16KB] = 32KB.
// ---------------------------------------------------------------------------
#define SM_A    0
#define SM_B    65536
#define SM_SCL  (SM_B + 32768)
#define SM_SFT  (SM_SCL + 256)
#define SM_TOT  (SM_SFT + 256)

__device__ __forceinline__ void stage_offset(
    int kk, int buf, int v0, int tid, uint32_t sbase,
    const __half* __restrict__ xa, const uint2* __restrict__ wfrag)
{
    int row = tid;                       // 0..255, one row per thread
    int vv  = v0 + row;
    int n = (vv < Nq) ? __ldg(&g_nbr[kk * Nq + vv]) : -1;
    const __half* src = xa + (size_t)(n < 0 ? 0 : n) * Cq;
    uint32_t srcsz = (n >= 0) ? 16u : 0u;
    uint32_t dbase = sbase + SM_A + buf * 32768 + row * 128;
    uint32_t swz = (row & 7) << 4;
    #pragma unroll
    for (int j = 0; j < 8; j++)
        cp16(dbase + (((uint32_t)(j << 4)) ^ swz), src + j * 8, srcsz);
    const char* wsrc = (const char*)(wfrag + kk * 2048) + tid * 64;
    uint32_t wdst = sbase + SM_B + buf * 16384 + tid * 64;
    #pragma unroll
    for (int j = 0; j < 4; j++)
        cp16(wdst + j * 16, wsrc + j * 16, 16u);
}

__global__ void __launch_bounds__(256, 2) conv_mma_kernel(
    const __half* __restrict__ xa,
    const uint2* __restrict__ wfrag,
    const float* __restrict__ bias,
    const float* __restrict__ gg, const float* __restrict__ be,
    const float* __restrict__ mm, const float* __restrict__ vv,
    float* __restrict__ out_f32,
    __half* __restrict__ oa,
    int outmode)
{
    extern __shared__ char smc[];
    const uint32_t sbase = smem_u32(smc);
    const int tid  = threadIdx.x;
    const int lane = tid & 31;
    const int warp = tid >> 5;
    const int v0   = blockIdx.x * 256;

    float* s_scale = (float*)(smc + SM_SCL);
    float* s_shift = (float*)(smc + SM_SFT);
    if (tid < Cq) {
        float sc = gg[tid] * rsqrtf(vv[tid] + EPSq);
        s_scale[tid] = sc;
        s_shift[tid] = (bias[tid] - mm[tid]) * sc + be[tid];
    }

    stage_offset(0, 0, v0, tid, sbase, xa, wfrag);
    cp_commit();
    stage_offset(1, 1, v0, tid, sbase, xa, wfrag);
    cp_commit();

    float d[2][8][4];
    #pragma unroll
    for (int rt = 0; rt < 2; rt++)
        #pragma unroll
        for (int i = 0; i < 8; i++)
            #pragma unroll
            for (int j = 0; j < 4; j++) d[rt][i][j] = 0.f;

    const int rowl = (lane & 7) | (lane & 8);          // 0..15
    const int row  = warp * 16 + rowl;                 // row-tile 0 row
    const uint32_t swz  = (row & 7) << 4;              // same for row+128
    const uint32_t colh = (lane & 16);

    for (int k = 0; k < Kq; k++) {
        const int buf = k & 1;
        if (k == Kq - 1) asm volatile("cp.async.wait_group 0;" ::: "memory");
        else             asm volatile("cp.async.wait_group 1;" ::: "memory");
        __syncthreads();

        const uint32_t sa0 = sbase + SM_A + buf * 32768 + row * 128;
        const uint32_t sa1 = sa0 + 128 * 128;
        const uint2* sb = (const uint2*)(smc + SM_B + buf * 16384);

        #pragma unroll
        for (int kc = 0; kc < 4; kc++) {
            uint32_t boff = ((uint32_t)((kc << 5) | colh)) ^ swz;
            uint32_t a0[4], a1[4];
            ldm_x4(a0, sa0 + boff);
            ldm_x4(a1, sa1 + boff);
            #pragma unroll
            for (int n8 = 0; n8 < 8; n8++) {
                uint2 bh = sb[(kc * 8 + n8) * 32 + lane];
                uint2 bl = sb[((4 + kc) * 8 + n8) * 32 + lane];
                mma_f16(d[0][n8], a0, bh.x, bh.y);
                mma_f16(d[0][n8], a0, bl.x, bl.y);
                mma_f16(d[1][n8], a1, bh.x, bh.y);
                mma_f16(d[1][n8], a1, bl.x, bl.y);
            }
        }
        __syncthreads();
        if (k < Kq - 2) {
            stage_offset(k + 2, buf, v0, tid, sbase, xa, wfrag);
            cp_commit();
        }
    }

    // epilogue: BN + ReLU
    #pragma unroll
    for (int rt = 0; rt < 2; rt++) {
        const int r0 = v0 + rt * 128 + warp * 16 + (lane >> 2);
        const int r1 = r0 + 8;
        #pragma unroll
        for (int n8 = 0; n8 < 8; n8++) {
            int col = n8 * 8 + (lane & 3) * 2;
            float sc0 = s_scale[col], sc1 = s_scale[col + 1];
            float sh0 = s_shift[col], sh1 = s_shift[col + 1];
            float o00 = fmaxf(fmaf(d[rt][n8][0], sc0, sh0), 0.f);
            float o01 = fmaxf(fmaf(d[rt][n8][1], sc1, sh1), 0.f);
            float o10 = fmaxf(fmaf(d[rt][n8][2], sc0, sh0), 0.f);
            float o11 = fmaxf(fmaf(d[rt][n8][3], sc1, sh1), 0.f);
            if (outmode == 0) {
                if (r0 < Nq)
                    *(float2*)(out_f32 + (size_t)r0 * Cq + col) = make_float2(o00, o01);
                if (r1 < Nq)
                    *(float2*)(out_f32 + (size_t)r1 * Cq + col) = make_float2(o10, o11);
            } else {
                __half2 h0; h0.x = __float2half_rn(o00); h0.y = __float2half_rn(o01);
                __half2 h1; h1.x = __float2half_rn(o10); h1.y = __float2half_rn(o11);
                if (r0 < Nq) *(__half2*)(oa + (size_t)r0 * Cq + col) = h0;
                if (r1 < Nq) *(__half2*)(oa + (size_t)r1 * Cq + col) = h1;
            }
        }
    }
}

// ---------------------------------------------------------------------------
extern "C" void kernel_launch(void* const* d_in, const int* in_sizes, int n_in,
                              void* d_out, int out_size)
{
    const float* feats  = (const float*)d_in[0];
    const int*   coords = (const int*)  d_in[1];
    const float* w1 = (const float*)d_in[2];
    const float* b1 = (const float*)d_in[3];
    const float* g1 = (const float*)d_in[4];
    const float* be1= (const float*)d_in[5];
    const float* m1 = (const float*)d_in[6];
    const float* v1 = (const float*)d_in[7];
    const float* w2 = (const float*)d_in[8];
    const float* b2 = (const float*)d_in[9];
    const float* g2 = (const float*)d_in[10];
    const float* be2= (const float*)d_in[11];
    const float* m2 = (const float*)d_in[12];
    const float* v2 = (const float*)d_in[13];
    const float* w3 = (const float*)d_in[14];
    const float* b3 = (const float*)d_in[15];
    const float* g3 = (const float*)d_in[16];
    const float* be3= (const float*)d_in[17];
    const float* m3 = (const float*)d_in[18];
    const float* v3 = (const float*)d_in[19];
    float* out = (float*)d_out;

    cudaFuncSetAttribute(conv_mma_kernel,
                         cudaFuncAttributeMaxDynamicSharedMemorySize, SM_TOT);

    uint2 *wf2, *wf3;
    cudaGetSymbolAddress((void**)&wf2, g_wf2);
    cudaGetSymbolAddress((void**)&wf3, g_wf3);
    __half *a1, *a2;
    cudaGetSymbolAddress((void**)&a1, g_a1);
    cudaGetSymbolAddress((void**)&a2, g_a2);

    init_table_kernel<<<4096, 256>>>();
    scatter_kernel<<<(Nq + 255) / 256, 256>>>(coords);
    prep_w_kernel<<<(Kq * 2048 + 255) / 256, 256>>>(w2, wf2);
    prep_w_kernel<<<(Kq * 2048 + 255) / 256, 256>>>(w3, wf3);
    build_nbr_kernel<<<(Nq + 255) / 256, 256>>>(coords);

    layer1_kernel<<<Nq / 128, 256>>>(feats, w1, b1, g1, be1, m1, v1, a1);
    const int grid = (Nq + 255) / 256;
    conv_mma_kernel<<<grid, 256, SM_TOT>>>(a1, wf2, b2, g2, be2, m2, v2,
                                           nullptr, a2, 1);
    conv_mma_kernel<<<grid, 256, SM_TOT>>>(a2, wf3, b3, g3, be3, m3, v3,
                                           out, nullptr, 0);
}

// round 6
// speedup vs baseline: 2.6131x; 1.6085x over previous
#include <cuda_runtime.h>
#include <cuda_fp16.h>
#include <cstdint>

#define Nq 400000
#define Kq 27
#define Cq 64
#define Dq 128
#define Hq 128
#define Wq 128
#define EPSq 1e-5f
#define TABLE_SIZE (2 * Dq * Hq * Wq)   // 4,194,304

// ---- scratch (device globals; allocation-free rule) ----
__device__ int   g_table[TABLE_SIZE];
__device__ int   g_nbr[Kq * Nq];
// activations: single fp16
__device__ __half g_a1[(size_t)Nq * Cq];
__device__ __half g_a2[(size_t)Nq * Cq];
// pre-packed B fragments (fp16, single term): [k][kc(4)][n8(8)][lane(32)] x uint2
__device__ uint2 g_wf2[Kq * 1024];
__device__ uint2 g_wf3[Kq * 1024];

// ---------------------------------------------------------------------------
// helpers
// ---------------------------------------------------------------------------
__device__ __forceinline__ uint32_t smem_u32(const void* p) {
    uint32_t a;
    asm("{ .reg .u64 t; cvta.to.shared.u64 t, %1; cvt.u32.u64 %0, t; }" : "=r"(a) : "l"(p));
    return a;
}

__device__ __forceinline__ void mma_f16(float* d, const uint32_t* a, uint32_t b0, uint32_t b1) {
    asm volatile(
        "mma.sync.aligned.m16n8k16.row.col.f32.f16.f16.f32 "
        "{%0,%1,%2,%3}, {%4,%5,%6,%7}, {%8,%9}, {%0,%1,%2,%3};"
        : "+f"(d[0]), "+f"(d[1]), "+f"(d[2]), "+f"(d[3])
        : "r"(a[0]), "r"(a[1]), "r"(a[2]), "r"(a[3]), "r"(b0), "r"(b1));
}

__device__ __forceinline__ void ldm_x4(uint32_t* a, uint32_t addr) {
    asm volatile(
        "ldmatrix.sync.aligned.m8n8.x4.shared.b16 {%0,%1,%2,%3}, [%4];"
        : "=r"(a[0]), "=r"(a[1]), "=r"(a[2]), "=r"(a[3]) : "r"(addr));
}

__device__ __forceinline__ void cp16(uint32_t dst, const void* src, uint32_t srcsize) {
    asm volatile("cp.async.cg.shared.global [%0], [%1], 16, %2;"
                 :: "r"(dst), "l"(src), "r"(srcsize) : "memory");
}
__device__ __forceinline__ void cp_commit() {
    asm volatile("cp.async.commit_group;" ::: "memory");
}

// ---------------------------------------------------------------------------
// rulebook
// ---------------------------------------------------------------------------
__global__ void init_table_kernel() {
    int i = blockIdx.x * blockDim.x + threadIdx.x;
    ((int4*)g_table)[i] = make_int4(-1, -1, -1, -1);
}

__global__ void scatter_kernel(const int* __restrict__ coords) {
    int i = blockIdx.x * blockDim.x + threadIdx.x;
    if (i >= Nq) return;
    int b = coords[i * 4 + 0], z = coords[i * 4 + 1];
    int y = coords[i * 4 + 2], x = coords[i * 4 + 3];
    g_table[((b * Dq + z) * Hq + y) * Wq + x] = i;
}

__global__ void build_nbr_kernel(const int* __restrict__ coords) {
    int i = blockIdx.x * blockDim.x + threadIdx.x;
    if (i >= Nq) return;
    int b = coords[i * 4 + 0], z = coords[i * 4 + 1];
    int y = coords[i * 4 + 2], x = coords[i * 4 + 3];
    #pragma unroll
    for (int k = 0; k < Kq; k++) {
        int dz = k / 9 - 1, dy = (k / 3) % 3 - 1, dx = k % 3 - 1;
        int nz = z + dz, ny = y + dy, nx = x + dx;
        int r = -1;
        if (nz >= 0 && nz < Dq && ny >= 0 && ny < Hq && nx >= 0 && nx < Wq)
            r = g_table[((b * Dq + nz) * Hq + ny) * Wq + nx];
        g_nbr[k * Nq + i] = r;
    }
}

// ---------------------------------------------------------------------------
// weight prep: w[k][cin][cout] fp32 -> mma B fragments, single fp16
// ---------------------------------------------------------------------------
__global__ void prep_w_kernel(const float* __restrict__ w, uint2* __restrict__ frag) {
    int idx = blockIdx.x * blockDim.x + threadIdx.x;
    if (idx >= Kq * 1024) return;
    int lane = idx & 31;
    int n8   = (idx >> 5) & 7;
    int kc   = (idx >> 8) & 3;
    int k    = idx >> 10;

    int n  = n8 * 8 + (lane >> 2);
    int c0 = kc * 16 + (lane & 3) * 2;
    uint32_t r[2];
    #pragma unroll
    for (int h = 0; h < 2; h++) {
        uint32_t packed = 0;
        #pragma unroll
        for (int e = 0; e < 2; e++) {
            float x = w[(k * 64 + (c0 + h * 8 + e)) * 64 + n];
            __half hv = __float2half_rn(x);
            uint16_t bits = *(uint16_t*)&hv;
            packed |= (uint32_t)bits << (16 * e);
        }
        r[h] = packed;
    }
    frag[idx] = make_uint2(r[0], r[1]);
}

// ---------------------------------------------------------------------------
// layer 1 (cin=1): 128-voxel tiles, 256 threads, writes single fp16
// ---------------------------------------------------------------------------
__global__ void __launch_bounds__(256) layer1_kernel(
    const float* __restrict__ feats, const float* __restrict__ w,
    const float* __restrict__ bias,
    const float* __restrict__ gg, const float* __restrict__ be,
    const float* __restrict__ mm, const float* __restrict__ vv,
    __half* __restrict__ oa)
{
    __shared__ float s_w[Kq * Cq];
    __shared__ float s_f[Kq * 128];
    __shared__ float s_scale[Cq], s_shift[Cq];

    const int tid = threadIdx.x;
    const int v0  = blockIdx.x * 128;

    if (tid < Cq) {
        float sc = gg[tid] * rsqrtf(vv[tid] + EPSq);
        s_scale[tid] = sc;
        s_shift[tid] = (bias[tid] - mm[tid]) * sc + be[tid];
    }
    for (int i = tid; i < Kq * Cq; i += 256) s_w[i] = w[i];

    #pragma unroll 7
    for (int idx = tid; idx < Kq * 128; idx += 256) {
        int k = idx >> 7, v = idx & 127;
        int n = g_nbr[k * Nq + v0 + v];
        s_f[idx] = (n >= 0) ? feats[n] : 0.f;
    }
    __syncthreads();

    const int c  = tid & 63;
    const int vg = tid >> 6;
    float acc[32];
    #pragma unroll
    for (int i = 0; i < 32; i++) acc[i] = 0.f;

    for (int k = 0; k < Kq; k++) {
        float wk = s_w[k * Cq + c];
        const float* fp = &s_f[k * 128 + vg * 32];
        #pragma unroll
        for (int i = 0; i < 32; i++) acc[i] = fmaf(fp[i], wk, acc[i]);
    }
    const float sc = s_scale[c], sh = s_shift[c];
    #pragma unroll
    for (int i = 0; i < 32; i++) {
        float r = fmaxf(fmaf(acc[i], sc, sh), 0.f);
        oa[(size_t)(v0 + vg * 32 + i) * Cq + c] = __float2half_rn(r);
    }
}

// ---------------------------------------------------------------------------
// conv64 via mma.sync fp16 single-term. 256 voxels/CTA, 256 threads.
// smem: A [2 buf][256 rows][128B swizzled] = 64KB, B [2 buf][8KB] = 16KB.
// ---------------------------------------------------------------------------
#define SM_A    0
#define SM_B    65536
#define SM_SCL  (SM_B + 16384)
#define SM_SFT  (SM_SCL + 256)
#define SM_TOT  (SM_SFT + 256)

__device__ __forceinline__ void stage_offset(
    int kk, int buf, int v0, int tid, uint32_t sbase,
    const __half* __restrict__ xa, const uint2* __restrict__ wfrag)
{
    int row = tid;                       // 0..255
    int vv  = v0 + row;
    int n = (vv < Nq) ? __ldg(&g_nbr[kk * Nq + vv]) : -1;
    const __half* src = xa + (size_t)(n < 0 ? 0 : n) * Cq;
    uint32_t srcsz = (n >= 0) ? 16u : 0u;
    uint32_t dbase = sbase + SM_A + buf * 32768 + row * 128;
    uint32_t swz = (row & 7) << 4;
    #pragma unroll
    for (int j = 0; j < 8; j++)
        cp16(dbase + (((uint32_t)(j << 4)) ^ swz), src + j * 8, srcsz);
    // B blob: 8KB per offset -> 32B per thread
    const char* wsrc = (const char*)(wfrag + kk * 1024) + tid * 32;
    uint32_t wdst = sbase + SM_B + buf * 8192 + tid * 32;
    cp16(wdst,      wsrc,      16u);
    cp16(wdst + 16, wsrc + 16, 16u);
}

__global__ void __launch_bounds__(256, 2) conv_mma_kernel(
    const __half* __restrict__ xa,
    const uint2* __restrict__ wfrag,
    const float* __restrict__ bias,
    const float* __restrict__ gg, const float* __restrict__ be,
    const float* __restrict__ mm, const float* __restrict__ vv,
    float* __restrict__ out_f32,
    __half* __restrict__ oa,
    int outmode)
{
    extern __shared__ char smc[];
    const uint32_t sbase = smem_u32(smc);
    const int tid  = threadIdx.x;
    const int lane = tid & 31;
    const int warp = tid >> 5;
    const int v0   = blockIdx.x * 256;

    float* s_scale = (float*)(smc + SM_SCL);
    float* s_shift = (float*)(smc + SM_SFT);
    if (tid < Cq) {
        float sc = gg[tid] * rsqrtf(vv[tid] + EPSq);
        s_scale[tid] = sc;
        s_shift[tid] = (bias[tid] - mm[tid]) * sc + be[tid];
    }

    stage_offset(0, 0, v0, tid, sbase, xa, wfrag);
    cp_commit();
    stage_offset(1, 1, v0, tid, sbase, xa, wfrag);
    cp_commit();

    float d[2][8][4];
    #pragma unroll
    for (int rt = 0; rt < 2; rt++)
        #pragma unroll
        for (int i = 0; i < 8; i++)
            #pragma unroll
            for (int j = 0; j < 4; j++) d[rt][i][j] = 0.f;

    const int rowl = (lane & 7) | (lane & 8);          // 0..15
    const int row  = warp * 16 + rowl;
    const uint32_t swz  = (row & 7) << 4;
    const uint32_t colh = (lane & 16);

    for (int k = 0; k < Kq; k++) {
        const int buf = k & 1;
        if (k == Kq - 1) asm volatile("cp.async.wait_group 0;" ::: "memory");
        else             asm volatile("cp.async.wait_group 1;" ::: "memory");
        __syncthreads();

        const uint32_t sa0 = sbase + SM_A + buf * 32768 + row * 128;
        const uint32_t sa1 = sa0 + 128 * 128;
        const uint2* sb = (const uint2*)(smc + SM_B + buf * 8192);

        #pragma unroll
        for (int kc = 0; kc < 4; kc++) {
            uint32_t boff = ((uint32_t)((kc << 5) | colh)) ^ swz;
            uint32_t a0[4], a1[4];
            ldm_x4(a0, sa0 + boff);
            ldm_x4(a1, sa1 + boff);
            #pragma unroll
            for (int n8 = 0; n8 < 8; n8++) {
                uint2 bh = sb[(kc * 8 + n8) * 32 + lane];
                mma_f16(d[0][n8], a0, bh.x, bh.y);
                mma_f16(d[1][n8], a1, bh.x, bh.y);
            }
        }
        __syncthreads();
        if (k < Kq - 2) {
            stage_offset(k + 2, buf, v0, tid, sbase, xa, wfrag);
            cp_commit();
        }
    }

    // epilogue: BN + ReLU
    #pragma unroll
    for (int rt = 0; rt < 2; rt++) {
        const int r0 = v0 + rt * 128 + warp * 16 + (lane >> 2);
        const int r1 = r0 + 8;
        #pragma unroll
        for (int n8 = 0; n8 < 8; n8++) {
            int col = n8 * 8 + (lane & 3) * 2;
            float sc0 = s_scale[col], sc1 = s_scale[col + 1];
            float sh0 = s_shift[col], sh1 = s_shift[col + 1];
            float o00 = fmaxf(fmaf(d[rt][n8][0], sc0, sh0), 0.f);
            float o01 = fmaxf(fmaf(d[rt][n8][1], sc1, sh1), 0.f);
            float o10 = fmaxf(fmaf(d[rt][n8][2], sc0, sh0), 0.f);
            float o11 = fmaxf(fmaf(d[rt][n8][3], sc1, sh1), 0.f);
            if (outmode == 0) {
                if (r0 < Nq)
                    *(float2*)(out_f32 + (size_t)r0 * Cq + col) = make_float2(o00, o01);
                if (r1 < Nq)
                    *(float2*)(out_f32 + (size_t)r1 * Cq + col) = make_float2(o10, o11);
            } else {
                __half2 h0; h0.x = __float2half_rn(o00); h0.y = __float2half_rn(o01);
                __half2 h1; h1.x = __float2half_rn(o10); h1.y = __float2half_rn(o11);
                if (r0 < Nq) *(__half2*)(oa + (size_t)r0 * Cq + col) = h0;
                if (r1 < Nq) *(__half2*)(oa + (size_t)r1 * Cq + col) = h1;
            }
        }
    }
}

// ---------------------------------------------------------------------------
extern "C" void kernel_launch(void* const* d_in, const int* in_sizes, int n_in,
                              void* d_out, int out_size)
{
    const float* feats  = (const float*)d_in[0];
    const int*   coords = (const int*)  d_in[1];
    const float* w1 = (const float*)d_in[2];
    const float* b1 = (const float*)d_in[3];
    const float* g1 = (const float*)d_in[4];
    const float* be1= (const float*)d_in[5];
    const float* m1 = (const float*)d_in[6];
    const float* v1 = (const float*)d_in[7];
    const float* w2 = (const float*)d_in[8];
    const float* b2 = (const float*)d_in[9];
    const float* g2 = (const float*)d_in[10];
    const float* be2= (const float*)d_in[11];
    const float* m2 = (const float*)d_in[12];
    const float* v2 = (const float*)d_in[13];
    const float* w3 = (const float*)d_in[14];
    const float* b3 = (const float*)d_in[15];
    const float* g3 = (const float*)d_in[16];
    const float* be3= (const float*)d_in[17];
    const float* m3 = (const float*)d_in[18];
    const float* v3 = (const float*)d_in[19];
    float* out = (float*)d_out;

    cudaFuncSetAttribute(conv_mma_kernel,
                         cudaFuncAttributeMaxDynamicSharedMemorySize, SM_TOT);

    uint2 *wf2, *wf3;
    cudaGetSymbolAddress((void**)&wf2, g_wf2);
    cudaGetSymbolAddress((void**)&wf3, g_wf3);
    __half *a1, *a2;
    cudaGetSymbolAddress((void**)&a1, g_a1);
    cudaGetSymbolAddress((void**)&a2, g_a2);

    init_table_kernel<<<4096, 256>>>();
    scatter_kernel<<<(Nq + 255) / 256, 256>>>(coords);
    prep_w_kernel<<<(Kq * 1024 + 255) / 256, 256>>>(w2, wf2);
    prep_w_kernel<<<(Kq * 1024 + 255) / 256, 256>>>(w3, wf3);
    build_nbr_kernel<<<(Nq + 255) / 256, 256>>>(coords);

    layer1_kernel<<<Nq / 128, 256>>>(feats, w1, b1, g1, be1, m1, v1, a1);
    const int grid = (Nq + 255) / 256;
    conv_mma_kernel<<<grid, 256, SM_TOT>>>(a1, wf2, b2, g2, be2, m2, v2,
                                           nullptr, a2, 1);
    conv_mma_kernel<<<grid, 256, SM_TOT>>>(a2, wf3, b3, g3, be3, m3, v3,
                                           out, nullptr, 0);
}

// round 7
// speedup vs baseline: 2.9584x; 1.1321x over previous
#include <cuda_runtime.h>
#include <cuda_fp16.h>
#include <cstdint>

#define Nq 400000
#define Kq 27
#define Cq 64
#define Dq 128
#define Hq 128
#define Wq 128
#define EPSq 1e-5f
#define TABLE_SIZE (2 * Dq * Hq * Wq)   // 4,194,304
#define CAPq 2600000                    // pair capacity (E ~ 1.39M expected)
#define MAXCHUNK 24576
#define PA_GRID 16384

// ---- scratch (device globals; allocation-free rule) ----
__device__ int   g_table[TABLE_SIZE];
__device__ int   g_nbr[Kq * Nq];          // rulebook, k-major
__device__ int   g_kcnt[32];              // per-offset pair counts
__device__ int   g_kpos[32];              // fill cursors
__device__ int   g_koff[33];              // CSR offsets per offset
__device__ int   g_nT;                    // total 128-row chunks
__device__ int   g_chunk_k[MAXCHUNK];
__device__ int   g_chunk_s[MAXCHUNK];     // start pair index of chunk
__device__ int   g_pin[CAPq];             // pair -> input voxel
__device__ int   g_plist[(size_t)Nq * Kq];// voxel-major pair ids (stride 27)
__device__ int   g_deg[Nq];
__device__ __half g_stg[(size_t)CAPq * Cq];  // staged conv partials (fp16)
__device__ __half g_a1[(size_t)Nq * Cq];
__device__ __half g_a2[(size_t)Nq * Cq];
__device__ uint2 g_wf2[Kq * 1024];        // B fragments fp16
__device__ uint2 g_wf3[Kq * 1024];

// ---------------------------------------------------------------------------
// helpers
// ---------------------------------------------------------------------------
__device__ __forceinline__ uint32_t smem_u32(const void* p) {
    uint32_t a;
    asm("{ .reg .u64 t; cvta.to.shared.u64 t, %1; cvt.u32.u64 %0, t; }" : "=r"(a) : "l"(p));
    return a;
}
__device__ __forceinline__ void mma_f16(float* d, const uint32_t* a, uint32_t b0, uint32_t b1) {
    asm volatile(
        "mma.sync.aligned.m16n8k16.row.col.f32.f16.f16.f32 "
        "{%0,%1,%2,%3}, {%4,%5,%6,%7}, {%8,%9}, {%0,%1,%2,%3};"
        : "+f"(d[0]), "+f"(d[1]), "+f"(d[2]), "+f"(d[3])
        : "r"(a[0]), "r"(a[1]), "r"(a[2]), "r"(a[3]), "r"(b0), "r"(b1));
}
__device__ __forceinline__ void ldm_x4(uint32_t* a, uint32_t addr) {
    asm volatile(
        "ldmatrix.sync.aligned.m8n8.x4.shared.b16 {%0,%1,%2,%3}, [%4];"
        : "=r"(a[0]), "=r"(a[1]), "=r"(a[2]), "=r"(a[3]) : "r"(addr));
}
__device__ __forceinline__ void cp16(uint32_t dst, const void* src, uint32_t srcsize) {
    asm volatile("cp.async.cg.shared.global [%0], [%1], 16, %2;"
                 :: "r"(dst), "l"(src), "r"(srcsize) : "memory");
}
__device__ __forceinline__ void cp_commit() {
    asm volatile("cp.async.commit_group;" ::: "memory");
}
__device__ __forceinline__ void cp_wait0() {
    asm volatile("cp.async.wait_group 0;" ::: "memory");
}

// ---------------------------------------------------------------------------
// rulebook
// ---------------------------------------------------------------------------
__global__ void init_table_kernel() {
    int i = blockIdx.x * blockDim.x + threadIdx.x;
    ((int4*)g_table)[i] = make_int4(-1, -1, -1, -1);
    if (blockIdx.x == 0 && threadIdx.x < 32) g_kcnt[threadIdx.x] = 0;
}

__global__ void scatter_kernel(const int* __restrict__ coords) {
    int i = blockIdx.x * blockDim.x + threadIdx.x;
    if (i >= Nq) return;
    int b = coords[i * 4 + 0], z = coords[i * 4 + 1];
    int y = coords[i * 4 + 2], x = coords[i * 4 + 3];
    g_table[((b * Dq + z) * Hq + y) * Wq + x] = i;
}

// build neighbor table + per-offset histogram
__global__ void __launch_bounds__(256) build_nbr_kernel(const int* __restrict__ coords) {
    __shared__ int sh[Kq];
    if (threadIdx.x < Kq) sh[threadIdx.x] = 0;
    __syncthreads();
    int i = blockIdx.x * blockDim.x + threadIdx.x;
    if (i < Nq) {
        int b = coords[i * 4 + 0], z = coords[i * 4 + 1];
        int y = coords[i * 4 + 2], x = coords[i * 4 + 3];
        #pragma unroll
        for (int k = 0; k < Kq; k++) {
            int dz = k / 9 - 1, dy = (k / 3) % 3 - 1, dx = k % 3 - 1;
            int nz = z + dz, ny = y + dy, nx = x + dx;
            int r = -1;
            if (nz >= 0 && nz < Dq && ny >= 0 && ny < Hq && nx >= 0 && nx < Wq)
                r = g_table[((b * Dq + nz) * Hq + ny) * Wq + nx];
            g_nbr[k * Nq + i] = r;
            if (r >= 0) atomicAdd(&sh[k], 1);
        }
    }
    __syncthreads();
    if (threadIdx.x < Kq) atomicAdd(&g_kcnt[threadIdx.x], sh[threadIdx.x]);
}

// scan 27 counts, build chunk work-list
__global__ void kscan_kernel() {
    __shared__ int s_off[Kq + 1];
    __shared__ int s_cb[Kq + 1];
    if (threadIdx.x == 0) {
        int run = 0, cb = 0;
        for (int k = 0; k < Kq; k++) {
            s_off[k] = run; s_cb[k] = cb;
            g_koff[k] = run; g_kpos[k] = run;
            run += g_kcnt[k];
            cb  += (g_kcnt[k] + 127) >> 7;
        }
        s_off[Kq] = run; s_cb[Kq] = cb;
        g_koff[Kq] = run;
        g_nT = cb;
    }
    __syncthreads();
    for (int k = 0; k < Kq; k++) {
        int nc = s_cb[k + 1] - s_cb[k];
        for (int j = threadIdx.x; j < nc; j += blockDim.x) {
            g_chunk_k[s_cb[k] + j] = k;
            g_chunk_s[s_cb[k] + j] = s_off[k] + 128 * j;
        }
    }
}

// fill pair lists: g_pin (offset-major), g_plist/g_deg (voxel-major)
__global__ void __launch_bounds__(256) fill_pairs_kernel() {
    __shared__ int sh[Kq];      // local hist
    __shared__ int sp[Kq];      // local cursors (global positions)
    if (threadIdx.x < Kq) sh[threadIdx.x] = 0;
    __syncthreads();
    int i = blockIdx.x * blockDim.x + threadIdx.x;
    int rn[Kq];
    if (i < Nq) {
        #pragma unroll
        for (int k = 0; k < Kq; k++) {
            rn[k] = g_nbr[k * Nq + i];
            if (rn[k] >= 0) atomicAdd(&sh[k], 1);
        }
    }
    __syncthreads();
    if (threadIdx.x < Kq)
        sp[threadIdx.x] = atomicAdd(&g_kpos[threadIdx.x], sh[threadIdx.x]);
    __syncthreads();
    if (i < Nq) {
        int j = 0;
        #pragma unroll
        for (int k = 0; k < Kq; k++) {
            if (rn[k] >= 0) {
                int p = atomicAdd(&sp[k], 1);
                if (p < CAPq) {
                    g_pin[p] = rn[k];
                    g_plist[(size_t)i * Kq + j] = p;
                }
                j++;
            }
        }
        g_deg[i] = j;
    }
}

// ---------------------------------------------------------------------------
// weight prep: w[k][cin][cout] fp32 -> mma B fragments, single fp16
// ---------------------------------------------------------------------------
__global__ void prep_w_kernel(const float* __restrict__ w, uint2* __restrict__ frag) {
    int idx = blockIdx.x * blockDim.x + threadIdx.x;
    if (idx >= Kq * 1024) return;
    int lane = idx & 31;
    int n8   = (idx >> 5) & 7;
    int kc   = (idx >> 8) & 3;
    int k    = idx >> 10;
    int n  = n8 * 8 + (lane >> 2);
    int c0 = kc * 16 + (lane & 3) * 2;
    uint32_t r[2];
    #pragma unroll
    for (int h = 0; h < 2; h++) {
        uint32_t packed = 0;
        #pragma unroll
        for (int e = 0; e < 2; e++) {
            float x = w[(k * 64 + (c0 + h * 8 + e)) * 64 + n];
            __half hv = __float2half_rn(x);
            uint16_t bits = *(uint16_t*)&hv;
            packed |= (uint32_t)bits << (16 * e);
        }
        r[h] = packed;
    }
    frag[idx] = make_uint2(r[0], r[1]);
}

// ---------------------------------------------------------------------------
// layer 1 (cin=1): direct sparse FMA; 2 threads per voxel (32 channels each)
// ---------------------------------------------------------------------------
__global__ void __launch_bounds__(256) layer1_kernel(
    const float* __restrict__ feats, const float* __restrict__ w,
    const float* __restrict__ bias,
    const float* __restrict__ gg, const float* __restrict__ be,
    const float* __restrict__ mm, const float* __restrict__ vv,
    __half* __restrict__ oa)
{
    __shared__ float s_w[Kq * Cq];
    __shared__ float s_scale[Cq], s_shift[Cq];
    const int tid = threadIdx.x;
    if (tid < Cq) {
        float sc = gg[tid] * rsqrtf(vv[tid] + EPSq);
        s_scale[tid] = sc;
        s_shift[tid] = (bias[tid] - mm[tid]) * sc + be[tid];
    }
    for (int t = tid; t < Kq * Cq; t += 256) s_w[t] = w[t];
    __syncthreads();

    int idx = blockIdx.x * blockDim.x + tid;
    int v = idx >> 1;
    if (v >= Nq) return;
    int c0 = (idx & 1) * 32;

    float acc[32];
    #pragma unroll
    for (int c = 0; c < 32; c++) acc[c] = 0.f;

    #pragma unroll
    for (int k = 0; k < Kq; k++) {
        int n = g_nbr[k * Nq + v];
        if (n >= 0) {
            float f = __ldg(&feats[n]);
            const float* wr = &s_w[k * Cq + c0];
            #pragma unroll
            for (int c = 0; c < 32; c++) acc[c] = fmaf(f, wr[c], acc[c]);
        }
    }
    __half2 outp[16];
    #pragma unroll
    for (int c = 0; c < 32; c += 2) {
        float o0 = fmaxf(fmaf(acc[c],     s_scale[c0 + c],     s_shift[c0 + c]),     0.f);
        float o1 = fmaxf(fmaf(acc[c + 1], s_scale[c0 + c + 1], s_shift[c0 + c + 1]), 0.f);
        outp[c >> 1] = __floats2half2_rn(o0, o1);
    }
    uint4* dst = (uint4*)(oa + (size_t)v * Cq + c0);
    const uint4* srcp = (const uint4*)outp;
    dst[0] = srcp[0]; dst[1] = srcp[1]; dst[2] = srcp[2]; dst[3] = srcp[3];
}

// ---------------------------------------------------------------------------
// Phase A: compacted per-offset GEMM. chunk = (k, 128 pair-rows).
// 128 threads (4 warps, 32 rows each). Writes raw partials to g_stg (fp16).
// ---------------------------------------------------------------------------
__global__ void __launch_bounds__(128) phaseA_kernel(
    const __half* __restrict__ xa, const uint2* __restrict__ wfrag)
{
    __shared__ __align__(16) char s_a[128 * 128];   // 16KB gathered A rows
    __shared__ __align__(16) char s_b[8192];        // 8KB B fragments
    const uint32_t sa_base = smem_u32(s_a);
    const int tid  = threadIdx.x;
    const int lane = tid & 31;
    const int warp = tid >> 5;
    const int nT   = g_nT;

    for (int c = blockIdx.x; c < nT; c += gridDim.x) {
        int k    = g_chunk_k[c];
        int p0   = g_chunk_s[c];
        int pend = g_koff[k + 1];

        // gather A: thread t -> row t
        {
            int p = p0 + tid;
            int n = (p < pend) ? __ldg(&g_pin[p]) : -1;
            const __half* src = xa + (size_t)(n < 0 ? 0 : n) * Cq;
            uint32_t srcsz = (n >= 0) ? 16u : 0u;
            uint32_t dbase = sa_base + tid * 128;
            uint32_t swz = (tid & 7) << 4;
            #pragma unroll
            for (int j = 0; j < 8; j++)
                cp16(dbase + (((uint32_t)(j << 4)) ^ swz), src + j * 8, srcsz);
        }
        // stage B fragments: 8KB
        {
            const char* wsrc = (const char*)(wfrag + k * 1024) + tid * 64;
            uint32_t wdst = smem_u32(s_b) + tid * 64;
            #pragma unroll
            for (int j = 0; j < 4; j++)
                cp16(wdst + j * 16, wsrc + j * 16, 16u);
        }
        cp_commit();
        cp_wait0();
        __syncthreads();

        float d[2][8][4];
        #pragma unroll
        for (int rt = 0; rt < 2; rt++)
            #pragma unroll
            for (int i = 0; i < 8; i++)
                #pragma unroll
                for (int j = 0; j < 4; j++) d[rt][i][j] = 0.f;

        const int rowl = (lane & 7) | (lane & 8);
        const uint32_t colh = (lane & 16);
        const uint2* sb = (const uint2*)s_b;

        #pragma unroll
        for (int kc = 0; kc < 4; kc++) {
            int row0 = warp * 32 + rowl;
            uint32_t swz0 = (row0 & 7) << 4;
            uint32_t boff = ((uint32_t)((kc << 5) | colh)) ^ swz0;
            uint32_t a0[4], a1[4];
            ldm_x4(a0, sa_base + row0 * 128 + boff);
            ldm_x4(a1, sa_base + (row0 + 16) * 128 + boff);
            #pragma unroll
            for (int n8 = 0; n8 < 8; n8++) {
                uint2 bh = sb[(kc * 8 + n8) * 32 + lane];
                mma_f16(d[0][n8], a0, bh.x, bh.y);
                mma_f16(d[1][n8], a1, bh.x, bh.y);
            }
        }

        // store raw partials to staging (fp16), predicated on segment end
        #pragma unroll
        for (int rt = 0; rt < 2; rt++) {
            int r0 = warp * 32 + rt * 16 + (lane >> 2);
            int r1 = r0 + 8;
            bool v0 = (p0 + r0) < pend;
            bool v1 = (p0 + r1) < pend;
            __half* row0p = (__half*)(g_stg + (size_t)(p0 + r0) * Cq);
            __half* row1p = (__half*)(g_stg + (size_t)(p0 + r1) * Cq);
            #pragma unroll
            for (int n8 = 0; n8 < 8; n8++) {
                int col = n8 * 8 + (lane & 3) * 2;
                if (v0) *(__half2*)(row0p + col) = __floats2half2_rn(d[rt][n8][0], d[rt][n8][1]);
                if (v1) *(__half2*)(row1p + col) = __floats2half2_rn(d[rt][n8][2], d[rt][n8][3]);
            }
        }
        __syncthreads();
    }
}

// ---------------------------------------------------------------------------
// Phase B: per-voxel segmented reduction over staged rows + bias + BN + ReLU
// 4 threads per voxel, 16 channels each.
// ---------------------------------------------------------------------------
__global__ void __launch_bounds__(256) phaseB_kernel(
    const float* __restrict__ bias,
    const float* __restrict__ gg, const float* __restrict__ be,
    const float* __restrict__ mm, const float* __restrict__ vv,
    float* __restrict__ out_f32, __half* __restrict__ oa, int outmode)
{
    __shared__ float s_scale[Cq], s_shift[Cq];
    const int tid = threadIdx.x;
    if (tid < Cq) {
        float sc = gg[tid] * rsqrtf(vv[tid] + EPSq);
        s_scale[tid] = sc;
        s_shift[tid] = (bias[tid] - mm[tid]) * sc + be[tid];
    }
    __syncthreads();

    int v   = blockIdx.x * 64 + (tid >> 2);
    if (v >= Nq) return;
    int sub = tid & 3;
    int c0  = sub * 16;

    float acc[16];
    #pragma unroll
    for (int c = 0; c < 16; c++) acc[c] = 0.f;

    int deg = g_deg[v];
    const int* pl = &g_plist[(size_t)v * Kq];
    for (int j = 0; j < deg; j++) {
        int p = __ldg(&pl[j]);
        const uint4* row = (const uint4*)(g_stg + (size_t)p * Cq + c0);
        uint4 q0 = __ldg(&row[0]);
        uint4 q1 = __ldg(&row[1]);
        const __half2* h0 = (const __half2*)&q0;
        const __half2* h1 = (const __half2*)&q1;
        #pragma unroll
        for (int e = 0; e < 4; e++) {
            float2 f0 = __half22float2(h0[e]);
            float2 f1 = __half22float2(h1[e]);
            acc[e * 2 + 0] += f0.x;
            acc[e * 2 + 1] += f0.y;
            acc[8 + e * 2 + 0] += f1.x;
            acc[8 + e * 2 + 1] += f1.y;
        }
    }

    if (outmode == 0) {
        float4 o[4];
        #pragma unroll
        for (int e = 0; e < 4; e++) {
            float* oe = (float*)&o[e];
            #pragma unroll
            for (int u = 0; u < 4; u++) {
                int c = e * 4 + u;
                oe[u] = fmaxf(fmaf(acc[c], s_scale[c0 + c], s_shift[c0 + c]), 0.f);
            }
        }
        float4* dst = (float4*)(out_f32 + (size_t)v * Cq + c0);
        dst[0] = o[0]; dst[1] = o[1]; dst[2] = o[2]; dst[3] = o[3];
    } else {
        __half2 hp[8];
        #pragma unroll
        for (int e = 0; e < 8; e++) {
            int c = e * 2;
            float o0 = fmaxf(fmaf(acc[c],     s_scale[c0 + c],     s_shift[c0 + c]),     0.f);
            float o1 = fmaxf(fmaf(acc[c + 1], s_scale[c0 + c + 1], s_shift[c0 + c + 1]), 0.f);
            hp[e] = __floats2half2_rn(o0, o1);
        }
        uint4* dst = (uint4*)(oa + (size_t)v * Cq + c0);
        const uint4* srcp = (const uint4*)hp;
        dst[0] = srcp[0]; dst[1] = srcp[1];
    }
}

// ---------------------------------------------------------------------------
extern "C" void kernel_launch(void* const* d_in, const int* in_sizes, int n_in,
                              void* d_out, int out_size)
{
    const float* feats  = (const float*)d_in[0];
    const int*   coords = (const int*)  d_in[1];
    const float* w1 = (const float*)d_in[2];
    const float* b1 = (const float*)d_in[3];
    const float* g1 = (const float*)d_in[4];
    const float* be1= (const float*)d_in[5];
    const float* m1 = (const float*)d_in[6];
    const float* v1 = (const float*)d_in[7];
    const float* w2 = (const float*)d_in[8];
    const float* b2 = (const float*)d_in[9];
    const float* g2 = (const float*)d_in[10];
    const float* be2= (const float*)d_in[11];
    const float* m2 = (const float*)d_in[12];
    const float* v2 = (const float*)d_in[13];
    const float* w3 = (const float*)d_in[14];
    const float* b3 = (const float*)d_in[15];
    const float* g3 = (const float*)d_in[16];
    const float* be3= (const float*)d_in[17];
    const float* m3 = (const float*)d_in[18];
    const float* v3 = (const float*)d_in[19];
    float* out = (float*)d_out;

    uint2 *wf2, *wf3;
    cudaGetSymbolAddress((void**)&wf2, g_wf2);
    cudaGetSymbolAddress((void**)&wf3, g_wf3);
    __half *a1, *a2;
    cudaGetSymbolAddress((void**)&a1, g_a1);
    cudaGetSymbolAddress((void**)&a2, g_a2);

    // rulebook + pair lists
    init_table_kernel<<<4096, 256>>>();
    scatter_kernel<<<(Nq + 255) / 256, 256>>>(coords);
    prep_w_kernel<<<(Kq * 1024 + 255) / 256, 256>>>(w2, wf2);
    prep_w_kernel<<<(Kq * 1024 + 255) / 256, 256>>>(w3, wf3);
    build_nbr_kernel<<<(Nq + 255) / 256, 256>>>(coords);
    kscan_kernel<<<1, 256>>>();
    fill_pairs_kernel<<<(Nq + 255) / 256, 256>>>();

    // layer 1
    layer1_kernel<<<(Nq * 2 + 255) / 256, 256>>>(feats, w1, b1, g1, be1, m1, v1, a1);
    // layer 2
    phaseA_kernel<<<PA_GRID, 128>>>(a1, wf2);
    phaseB_kernel<<<(Nq + 63) / 64, 256>>>(b2, g2, be2, m2, v2, nullptr, a2, 1);
    // layer 3
    phaseA_kernel<<<PA_GRID, 128>>>(a2, wf3);
    phaseB_kernel<<<(Nq + 63) / 64, 256>>>(b3, g3, be3, m3, v3, out, nullptr, 0);
}